// round 9
// baseline (speedup 1.0000x reference)
#include <cuda_runtime.h>
#include <cstdint>

// Embedding gather: out[t, :] = weights[ids[t], :]
// ids: 16384 int32, weights: [50257,1024] fp32, out: [16384,1024] fp32
//
// R4 geometry (best: 17.9us): block=256 (one float4-column per thread),
// 4 tokens per block, grid 4096, default launch bounds (regs=32, occ ~79%).
// Single change vs R4: plain stores instead of __stcs. ids repeat every
// replay, so ~54MiB of weight rows stays L2-resident; hot set (54+64 MiB)
// fits the 126MB L2 -- letting output park dirty in L2 should remove most
// of the ~64MB/iter DRAM write traffic that currently bounds the kernel.

static constexpr int ROW_F4      = 256;  // float4 per row (1024 floats)
static constexpr int TOK_PER_BLK = 4;

__global__ void __launch_bounds__(256) embed_gather_kernel(
    const int* __restrict__ ids,
    const float4* __restrict__ w,
    float4* __restrict__ out,
    int n_tokens)
{
    const int col  = threadIdx.x;                 // 0..255
    const int tok0 = blockIdx.x * TOK_PER_BLK;

    if (tok0 + TOK_PER_BLK <= n_tokens) {
        const int r0 = __ldg(ids + tok0 + 0);
        const int r1 = __ldg(ids + tok0 + 1);
        const int r2 = __ldg(ids + tok0 + 2);
        const int r3 = __ldg(ids + tok0 + 3);

        float4 v0 = __ldg(w + (size_t)r0 * ROW_F4 + col);
        float4 v1 = __ldg(w + (size_t)r1 * ROW_F4 + col);
        float4 v2 = __ldg(w + (size_t)r2 * ROW_F4 + col);
        float4 v3 = __ldg(w + (size_t)r3 * ROW_F4 + col);

        out[(size_t)(tok0 + 0) * ROW_F4 + col] = v0;
        out[(size_t)(tok0 + 1) * ROW_F4 + col] = v1;
        out[(size_t)(tok0 + 2) * ROW_F4 + col] = v2;
        out[(size_t)(tok0 + 3) * ROW_F4 + col] = v3;
    } else {
        for (int t = tok0; t < n_tokens; ++t) {
            int r = __ldg(ids + t);
            out[(size_t)t * ROW_F4 + col] = __ldg(w + (size_t)r * ROW_F4 + col);
        }
    }
}

extern "C" void kernel_launch(void* const* d_in, const int* in_sizes, int n_in,
                              void* d_out, int out_size)
{
    const int*    ids = (const int*)d_in[0];
    const float4* w   = (const float4*)d_in[1];
    float4*       out = (float4*)d_out;

    int n_tokens = in_sizes[0];                                  // 16384
    int blocks   = (n_tokens + TOK_PER_BLK - 1) / TOK_PER_BLK;   // 4096
    embed_gather_kernel<<<blocks, 256>>>(ids, w, out, n_tokens);
}

// round 10
// speedup vs baseline: 1.1235x; 1.1235x over previous
#include <cuda_runtime.h>
#include <cstdint>

// Embedding gather: out[t, :] = weights[ids[t], :]
// ids: 16384 int32, weights: [50257,1024] fp32, out: [16384,1024] fp32
//
// Persistent grid-stride kernel, 2-stage register pipeline:
// each iteration issues the NEXT chunk's 4 gathers (LDG.128) before storing
// the CURRENT chunk's values, so gather latency overlaps a full iteration of
// useful work instead of being exposed per block (R4's batch-then-drain).
// Streaming stores (.cs) -- R9 showed output writes go to DRAM either way;
// .cs protects L2 weight-row residency across graph replays.

static constexpr int ROW_F4 = 256;   // float4 per row (1024 floats)

__global__ void __launch_bounds__(256) embed_persist_kernel(
    const int* __restrict__ ids,
    const float4* __restrict__ w,
    float4* __restrict__ out,
    int n_tokens)
{
    const int col    = threadIdx.x;            // 0..255: float4 column
    const int nchunk = n_tokens >> 2;          // 4 tokens per chunk (16384 % 4 == 0)
    const int stride = gridDim.x;

    int c = blockIdx.x;
    if (c >= nchunk) return;

    // ---- prologue: issue gathers for first chunk ----
    int t0 = c << 2;
    int r0 = __ldg(ids + t0 + 0);
    int r1 = __ldg(ids + t0 + 1);
    int r2 = __ldg(ids + t0 + 2);
    int r3 = __ldg(ids + t0 + 3);
    float4 v0 = __ldg(w + (size_t)r0 * ROW_F4 + col);
    float4 v1 = __ldg(w + (size_t)r1 * ROW_F4 + col);
    float4 v2 = __ldg(w + (size_t)r2 * ROW_F4 + col);
    float4 v3 = __ldg(w + (size_t)r3 * ROW_F4 + col);

    // ---- steady state ----
    for (int cn = c + stride; cn < nchunk; cn += stride) {
        const int t1 = cn << 2;
        // issue next chunk's loads FIRST (independent of v0..v3)
        int s0 = __ldg(ids + t1 + 0);
        int s1 = __ldg(ids + t1 + 1);
        int s2 = __ldg(ids + t1 + 2);
        int s3 = __ldg(ids + t1 + 3);
        float4 u0 = __ldg(w + (size_t)s0 * ROW_F4 + col);
        float4 u1 = __ldg(w + (size_t)s1 * ROW_F4 + col);
        float4 u2 = __ldg(w + (size_t)s2 * ROW_F4 + col);
        float4 u3 = __ldg(w + (size_t)s3 * ROW_F4 + col);

        // store previous chunk (v* were issued a full iteration ago)
        __stcs(out + (size_t)(t0 + 0) * ROW_F4 + col, v0);
        __stcs(out + (size_t)(t0 + 1) * ROW_F4 + col, v1);
        __stcs(out + (size_t)(t0 + 2) * ROW_F4 + col, v2);
        __stcs(out + (size_t)(t0 + 3) * ROW_F4 + col, v3);

        t0 = t1;
        v0 = u0; v1 = u1; v2 = u2; v3 = u3;
    }

    // ---- epilogue: store last chunk ----
    __stcs(out + (size_t)(t0 + 0) * ROW_F4 + col, v0);
    __stcs(out + (size_t)(t0 + 1) * ROW_F4 + col, v1);
    __stcs(out + (size_t)(t0 + 2) * ROW_F4 + col, v2);
    __stcs(out + (size_t)(t0 + 3) * ROW_F4 + col, v3);
}

extern "C" void kernel_launch(void* const* d_in, const int* in_sizes, int n_in,
                              void* d_out, int out_size)
{
    const int*    ids = (const int*)d_in[0];
    const float4* w   = (const float4*)d_in[1];
    float4*       out = (float4*)d_out;

    int n_tokens = in_sizes[0];                 // 16384
    int nchunk   = n_tokens >> 2;               // 4096

    // persistent-ish grid: ~8 CTAs per SM worth of blocks; loop covers the rest
    int blocks = 148 * 8;
    if (blocks > nchunk) blocks = nchunk;

    embed_persist_kernel<<<blocks, 256>>>(ids, w, out, n_tokens);
}